// round 9
// baseline (speedup 1.0000x reference)
#include <cuda_runtime.h>
#include <cstdint>

#define BB 16
#define FM 32
#define CC 128
#define HW 3136
#define ETA 0.1f
#define ALPHA_ 0.1f
#define THETA_ 0.1f
#define EPSF 1e-10f

typedef unsigned long long ull;

// ------------- scratch (static device globals; no allocation) -------------
__device__ float g_Ab[BB*CC*HW];        // clip(tile(symm_pad(A,2)) + eta*noise, 0)
__device__ float g_s[BB*CC];            // per-(b,c) spatial sum
__device__ float g_Kch[CC*CC*25];       // K_change [c][a][x*5+y]
__device__ float g_W2[CC*CC*25];        // conv2 weights [o][i][t]

// ---------------- packed f32x2 helpers ----------------
__device__ __forceinline__ ull pack2(float x, float y) {
    ull r; asm("mov.b64 %0, {%1,%2};" : "=l"(r) : "f"(x), "f"(y)); return r;
}
__device__ __forceinline__ void ffma2(ull& d, ull a, ull b) {
    asm("fma.rn.f32x2 %0, %1, %2, %3;" : "=l"(d) : "l"(a), "l"(b), "l"(d));
}
__device__ __forceinline__ float2 unpk(ull v) {
    float2 r; asm("mov.b64 {%0,%1}, %2;" : "=f"(r.x), "=f"(r.y) : "l"(v)); return r;
}

// symm_pad(.,2) index map on a 56 axis
__device__ __forceinline__ int m56(int h) {
    return h < 2 ? 3 - h : (h >= 54 ? 107 - h : h);
}
// pad_activations row/col map on the 60 axis
__device__ __forceinline__ int m60(int r) {
    return r < 4 ? 5 - r : (r < 56 ? r - 2 : 109 - r);
}

// ---------------- kernel 1: Ab + per-channel sums (+ zero g_Kch) -----------
__global__ void __launch_bounds__(224) k_prep(const float* __restrict__ A,
                                              const float* __restrict__ noise) {
    int bid = blockIdx.x;              // b*128 + c
    int tid = threadIdx.x;
    {
        int z0 = bid*200;
        if (tid < 200) g_Kch[z0 + tid] = 0.f;
    }
    int b = bid >> 7, c = bid & 127;
    int f = c & 31;
    const float* Ap = A + (size_t)(b*FM + f)*HW;
    const float* Np = noise + (size_t)bid*HW;
    float* Op = g_Ab + (size_t)bid*HW;

    int h0 = tid / 56, w0 = tid - (tid/56)*56;
    int mw = m56(w0);
    float sum = 0.f;
    #pragma unroll
    for (int j = 0; j < 14; j++) {
        int h = h0 + j*4;
        int idx = h*56 + w0;
        float v = fmaxf(Ap[m56(h)*56 + mw] + ETA*Np[idx], 0.f);
        Op[idx] = v;
        sum += v;
    }
    __shared__ float red[7];
    #pragma unroll
    for (int o = 16; o; o >>= 1) sum += __shfl_xor_sync(~0u, sum, o);
    if ((tid & 31) == 0) red[tid >> 5] = sum;
    __syncthreads();
    if (tid < 32) {
        float s2 = (tid < 7) ? red[tid] : 0.f;
        #pragma unroll
        for (int o = 4; o; o >>= 1) s2 += __shfl_xor_sync(0xffu, s2, o);
        if (tid == 0) g_s[bid] = s2;
    }
}

// ---------------- K_change: h-split tiles (8x7 rows) for 148-SM fill ------
// grid (b=16, cwt=2, z=32: at*8... z = hq*4 + at) = 1024 tiles
#define CHS 34
#define SAB_FLOATS (6*60*CHS)            // 12240
#define SAM_ULL (2*16*56)
#define SMEM_KCH (SAB_FLOATS*4 + SAM_ULL*8)   // 63296 B

__global__ void __launch_bounds__(256) k_kch() {
    int b = blockIdx.x, cwt = blockIdx.y;
    int z = blockIdx.z;
    int at = z & 3, hq = z >> 2;         // at 0..3, hq 0..7
    int h0 = hq * 7;
    int tid = threadIdx.x;
    int lane = tid & 31, wid = tid >> 5;
    int al = lane & 15;
    int cl = wid*2 + (lane >> 4);
    int a0 = at*32;

    extern __shared__ char smraw[];
    float* sAb  = (float*)smraw;                      // [6][60][34]
    ull*   sAm2 = (ull*)(smraw + SAB_FLOATS*4);       // [2][16][56]
    __shared__ int sC[16];

    if (tid < 16) {
        int f = cwt*16 + tid;
        float best = g_s[b*CC + f]; int wr = 0;
        #pragma unroll
        for (int r = 1; r < 4; r++) {
            float v = g_s[b*CC + r*FM + f];
            if (v > best) { best = v; wr = r; }
        }
        sC[tid] = wr*FM + f;
    }
    // zero only the halo columns (0,1,58,59) of all 6 slots
    for (int i = tid; i < 6*4*34; i += 256) {
        int s = i / 136, r = i - s*136;
        int c4 = r / 34, ch = r - c4*34;
        int col = (c4 < 2) ? c4 : 56 + c4;   // 0,1,58,59
        sAb[(s*60 + col)*CHS + ch] = 0.f;
    }
    __syncthreads();

    const float* AbB = g_Ab + (size_t)b*CC*HW;

    // prologue: rows h0-2 .. h0+2 -> slot r%6 (zeros for r<0)
    for (int r = h0 - 2; r <= h0 + 2; r++) {
        int slot = (r + 6) % 6;
        bool valid = r >= 0;
        for (int idx = tid; idx < 32*56; idx += 256) {
            int ch = idx / 56, col = idx - ch*56;
            sAb[(slot*60 + col + 2)*CHS + ch] =
                valid ? AbB[(size_t)(a0+ch)*HW + r*56 + col] : 0.f;
        }
    }
    // am row h0 -> buffer h0&1
    for (int idx = tid; idx < 16*56; idx += 256) {
        int cj = idx / 56, col = idx - cj*56;
        float v = AbB[(size_t)sC[cj]*HW + h0*56 + col];
        sAm2[(size_t)(h0 & 1)*16*56 + cj*56 + col] = pack2(v, v);
    }
    int myc = sC[cl];
    __syncthreads();

    ull acc[5][5];
    #pragma unroll
    for (int x = 0; x < 5; x++)
        #pragma unroll
        for (int y = 0; y < 5; y++) acc[x][y] = 0ull;

    for (int h = h0; h < h0 + 7; h++) {
        float pf[7];
        int prow = h + 3;
        bool pv = prow < 56;
        #pragma unroll
        for (int j = 0; j < 7; j++) {
            int idx = tid + j*256;
            int ch = idx / 56, col = idx - ch*56;
            pf[j] = pv ? AbB[(size_t)(a0+ch)*HW + prow*56 + col] : 0.f;
        }
        float pa[4];
        int arow = h + 1;
        #pragma unroll
        for (int j = 0; j < 4; j++) {
            int idx = tid + j*256;
            pa[j] = 0.f;
            if (arow < 56 && idx < 16*56) {
                int cj = idx / 56, co = idx - cj*56;
                pa[j] = AbB[(size_t)sC[cj]*HW + arow*56 + co];
            }
        }

        const char* rxp[5];
        #pragma unroll
        for (int x = 0; x < 5; x++) {
            int slot = (h + 8 - x) % 6;        // row h+2-x
            rxp[x] = (const char*)(sAb + slot*60*CHS + 2*al);
        }
        const ull* am = sAm2 + (size_t)(h & 1)*16*56 + cl*56;

        ull rg[5][5];
        #pragma unroll
        for (int x = 0; x < 5; x++)
            #pragma unroll
            for (int j = 0; j < 5; j++)
                rg[x][j] = *(const ull*)(rxp[x] + j*(CHS*4));

        #pragma unroll 1
        for (int wb = 0; wb < 55; wb += 5) {
            #pragma unroll
            for (int k = 0; k < 5; k++) {
                ull a = am[wb + k];
                #pragma unroll
                for (int x = 0; x < 5; x++) {
                    #pragma unroll
                    for (int y = 0; y < 5; y++)
                        ffma2(acc[x][y], a, rg[x][(k + 4 - y) % 5]);
                    rg[x][k] = *(const ull*)(rxp[x] + (wb + k + 5)*(CHS*4));
                }
            }
        }
        {
            ull a = am[55];
            #pragma unroll
            for (int x = 0; x < 5; x++)
                #pragma unroll
                for (int y = 0; y < 5; y++)
                    ffma2(acc[x][y], a, rg[x][(4 - y) % 5]);
        }

        {
            int slot = (h + 3) % 6;
            #pragma unroll
            for (int j = 0; j < 7; j++) {
                int idx = tid + j*256;
                int ch = idx / 56, col = idx - ch*56;
                sAb[(slot*60 + col + 2)*CHS + ch] = pf[j];
            }
            if (arow < 56) {
                ull* dst = sAm2 + (size_t)(arow & 1)*16*56;
                #pragma unroll
                for (int j = 0; j < 4; j++) {
                    int idx = tid + j*256;
                    if (idx < 16*56) {
                        int cj = idx / 56, co = idx - cj*56;
                        dst[cj*56 + co] = pack2(pa[j], pa[j]);
                    }
                }
            }
        }
        __syncthreads();
    }

    float* dst = g_Kch + ((size_t)myc*CC + (a0 + 2*al))*25;
    #pragma unroll
    for (int x = 0; x < 5; x++)
        #pragma unroll
        for (int y = 0; y < 5; y++) {
            float2 v = unpk(acc[x][y]);
            atomicAdd(&dst[x*5 + y],      v.x * (1.f/2048.f));
            atomicAdd(&dst[25 + x*5 + y], v.y * (1.f/2048.f));
        }
}

// ---------------- W2 = minmax(0.9*K1 + 0.1*minmax(K_change)) ---------------
__global__ void k_w2(const float* __restrict__ K) {
    int g = blockIdx.x*blockDim.x + threadIdx.x;
    if (g >= CC*CC) return;
    int o = g >> 7, i = g & 127;
    const float* kch = g_Kch + ((size_t)i*CC + o)*25;
    float v[25];
    float mn = 1e30f, mx = -1e30f;
    #pragma unroll
    for (int t = 0; t < 25; t++) { v[t] = kch[t]; mn = fminf(mn, v[t]); mx = fmaxf(mx, v[t]); }
    float inv = 1.f / (mx - mn + EPSF);
    const float* kk = K + ((size_t)o*CC + i)*25;   // K1[i][o] = K[o][i]
    float mn2 = 1e30f, mx2 = -1e30f;
    #pragma unroll
    for (int t = 0; t < 25; t++) {
        v[t] = (1.f - ALPHA_)*kk[t] + ALPHA_*((v[t] - mn)*inv);
        mn2 = fminf(mn2, v[t]); mx2 = fmaxf(mx2, v[t]);
    }
    float inv2 = 1.f / (mx2 - mn2 + EPSF);
    float* w = g_W2 + (size_t)g*25;
    #pragma unroll
    for (int t = 0; t < 25; t++) w[t] = (v[t] - mn2)*inv2;
}

// ---------------- winner-sparse conv2 + gather + output --------------------
// grid (b=16, pg=8); 256 threads = 4 i-quarters x (16 f-pairs x 4 q-groups of 14)
// LDS.128 everywhere: 11 LDS per 70 FFMA2 per stage
#define SIN6_ULL (6*32*62)             // 11904
#define SW4_ULL  (16*32*5*4)           // 10240 (w[0..3] aligned quads)
#define SW1_ULL  (16*32*5)             // 2560  (w[4])
#define SRED_ULL (3*64*14)             // 2688
#define SMEM_OUT ((SIN6_ULL + SW4_ULL + SW1_ULL + SRED_ULL)*8)   // 219136 B

__global__ void __launch_bounds__(256) k_out(float* __restrict__ out) {
    int b = blockIdx.x, pg = blockIdx.y;
    int tid = threadIdx.x;
    int g = tid >> 6;                  // i-quarter: i in [8g, 8g+8)
    int t6 = tid & 63;
    int fl = t6 >> 2;                  // f-pair 0..15
    int qg = t6 & 3;
    int q0 = qg * 14;

    extern __shared__ ull sh[];
    ull* sIn  = sh;                                   // [6][32][62] {v,v}
    ull* sW4  = sh + SIN6_ULL;                        // [16][32][5][4]
    ull* sW1  = sh + SIN6_ULL + SW4_ULL;              // [16][32][5]
    ull* sRed = sh + SIN6_ULL + SW4_ULL + SW1_ULL;    // [3][64][14]
    __shared__ int sFm[32];
    if (tid < 32) {
        float best = g_s[b*CC + tid]; int wr = 0;
        #pragma unroll
        for (int r = 1; r < 4; r++) {
            float v = g_s[b*CC + r*FM + tid];
            if (v > best) { best = v; wr = r; }
        }
        sFm[tid] = wr*FM + tid;
    }
    __syncthreads();

    // weights: w[0..3] in aligned quads, w[4] separate
    for (int idx = tid; idx < 16*800; idx += 256) {
        int fp = idx / 800, rem = idx - fp*800;
        int i = rem / 25, t = rem - i*25;
        int u = t / 5, y = t - u*5;
        float w0 = g_W2[((size_t)sFm[2*fp  ]*CC + sFm[i])*25 + t];
        float w1 = g_W2[((size_t)sFm[2*fp+1]*CC + sFm[i])*25 + t];
        ull pv = pack2(w0, w1);
        int o = (fp*32 + i)*5 + u;
        if (y < 4) sW4[o*4 + y] = pv;
        else       sW1[o]       = pv;
    }

    const float* AbB = g_Ab + (size_t)b*CC*HW;
    int p0 = pg * 7;

    #pragma unroll
    for (int r = 0; r < 5; r++) {
        int row = p0 + r, slot = row % 6, sr = m60(row);
        for (int idx = tid; idx < 32*60; idx += 256) {
            int i = idx / 60, col = idx - i*60;
            float v = AbB[(size_t)sFm[i]*HW + sr*56 + m60(col)];
            sIn[(slot*32 + i)*62 + col] = pack2(v, v);
        }
    }
    __syncthreads();

    int i0 = g*8;

    for (int p = p0; p < p0 + 7; p++) {
        // ---- prefetch padded row p+5 into regs ----
        float pfr[8];
        int prow = p + 5;
        bool pvr = prow < 60;
        int sr = pvr ? m60(prow) : 0;
        #pragma unroll
        for (int j = 0; j < 8; j++) {
            int idx = tid + j*256;
            pfr[j] = 0.f;
            if (pvr && idx < 32*60) {
                int i = idx / 60, col = idx - i*60;
                pfr[j] = AbB[(size_t)sFm[i]*HW + sr*56 + m60(col)];
            }
        }

        const ull* sb[5];
        #pragma unroll
        for (int u = 0; u < 5; u++)
            sb[u] = sIn + (size_t)((p + u) % 6)*32*62 + q0;

        ull acc[14];
        #pragma unroll
        for (int j = 0; j < 14; j++) acc[j] = 0ull;

        ull wA[5], vA[18], wB[5], vB[18];

        #define LOADW(i_, u_, W) { \
            int _o = ((fl*32 + (i_))*5 + (u_)); \
            ulonglong2 _a = *(const ulonglong2*)(sW4 + _o*4); \
            ulonglong2 _b = *(const ulonglong2*)(sW4 + _o*4 + 2); \
            (W)[0]=_a.x; (W)[1]=_a.y; (W)[2]=_b.x; (W)[3]=_b.y; \
            (W)[4] = sW1[_o]; }
        #define LOADV(i_, u_, V) { const ull* _rp = sb[(u_)] + (i_)*62; \
            _Pragma("unroll") for (int _c = 0; _c < 9; _c++) { \
                ulonglong2 _t = *(const ulonglong2*)(_rp + _c*2); \
                (V)[_c*2]=_t.x; (V)[_c*2+1]=_t.y; } }
        #define COMP(W, V) { \
            _Pragma("unroll") for (int _c = 0; _c < 18; _c++) { \
                ull _v = (V)[_c]; \
                _Pragma("unroll") for (int _y = 0; _y < 5; _y++) { \
                    int _j = _c - _y; \
                    if (_j >= 0 && _j <= 13) ffma2(acc[_j], _v, (W)[_y]); } } }

        LOADW(i0, 0, wA); LOADV(i0, 0, vA);
        #pragma unroll 1
        for (int ii = 0; ii < 8; ii += 2) {
            int i = i0 + ii;
            int inx = (ii == 6) ? i0 : (i + 2);   // dummy-safe final prefetch
            LOADW(i,   1, wB); LOADV(i,   1, vB); COMP(wA, vA);
            LOADW(i,   2, wA); LOADV(i,   2, vA); COMP(wB, vB);
            LOADW(i,   3, wB); LOADV(i,   3, vB); COMP(wA, vA);
            LOADW(i,   4, wA); LOADV(i,   4, vA); COMP(wB, vB);
            LOADW(i+1, 0, wB); LOADV(i+1, 0, vB); COMP(wA, vA);
            LOADW(i+1, 1, wA); LOADV(i+1, 1, vA); COMP(wB, vB);
            LOADW(i+1, 2, wB); LOADV(i+1, 2, vB); COMP(wA, vA);
            LOADW(i+1, 3, wA); LOADV(i+1, 3, vA); COMP(wB, vB);
            LOADW(i+1, 4, wB); LOADV(i+1, 4, vB); COMP(wA, vA);
            LOADW(inx, 0, wA); LOADV(inx, 0, vA); COMP(wB, vB);
        }
        #undef LOADW
        #undef LOADV
        #undef COMP

        // ---- commit prefetched row to slot (p+5)%6 ----
        if (pvr) {
            int slot = prow % 6;
            #pragma unroll
            for (int j = 0; j < 8; j++) {
                int idx = tid + j*256;
                if (idx < 32*60) {
                    int i = idx / 60, col = idx - i*60;
                    sIn[(slot*32 + i)*62 + col] = pack2(pfr[j], pfr[j]);
                }
            }
        }
        // ---- partial handoff: quarters 1..3 write, quarter 0 combines ----
        if (g != 0) {
            ull* red = sRed + (size_t)(g - 1)*64*14 + t6*14;
            #pragma unroll
            for (int j = 0; j < 14; j++) red[j] = acc[j];
        }
        __syncthreads();
        if (g == 0) {
            int f0 = 2*fl, f1 = f0 + 1;
            const float* a0r = AbB + (size_t)sFm[f0]*HW + p*56 + q0;
            const float* a1r = AbB + (size_t)sFm[f1]*HW + p*56 + q0;
            float* o0 = out + ((size_t)(b*FM + f0)*56 + p)*56 + q0;
            float* o1 = out + ((size_t)(b*FM + f1)*56 + p)*56 + q0;
            #pragma unroll
            for (int j = 0; j < 14; j++) {
                float2 v = unpk(acc[j]);
                #pragma unroll
                for (int q = 0; q < 3; q++) {
                    float2 r = unpk(sRed[(size_t)q*64*14 + t6*14 + j]);
                    v.x += r.x; v.y += r.y;
                }
                o0[j] = a0r[j] + THETA_ * (v.x * (1.f/32.f));
                o1[j] = a1r[j] + THETA_ * (v.y * (1.f/32.f));
            }
        }
        __syncthreads();
    }
}

// ---------------- launch ----------------
extern "C" void kernel_launch(void* const* d_in, const int* in_sizes, int n_in,
                              void* d_out, int out_size) {
    const float* A     = (const float*)d_in[0];
    const float* K     = (const float*)d_in[1];
    const float* noise = (const float*)d_in[2];
    float* out = (float*)d_out;

    k_prep<<<BB*CC, 224>>>(A, noise);

    cudaFuncSetAttribute(k_kch, cudaFuncAttributeMaxDynamicSharedMemorySize, SMEM_KCH);
    k_kch<<<dim3(BB, 2, 32), 256, SMEM_KCH>>>();

    k_w2<<<128, 128>>>(K);

    cudaFuncSetAttribute(k_out, cudaFuncAttributeMaxDynamicSharedMemorySize, SMEM_OUT);
    k_out<<<dim3(BB, 8), 256, SMEM_OUT>>>(out);
}

// round 10
// speedup vs baseline: 1.2423x; 1.2423x over previous
#include <cuda_runtime.h>
#include <cstdint>

#define BB 16
#define FM 32
#define CC 128
#define HW 3136
#define ETA 0.1f
#define ALPHA_ 0.1f
#define THETA_ 0.1f
#define EPSF 1e-10f

typedef unsigned long long ull;

// ------------- scratch (static device globals; no allocation) -------------
__device__ float g_Ab[BB*CC*HW];        // clip(tile(symm_pad(A,2)) + eta*noise, 0)
__device__ float g_s[BB*CC];            // per-(b,c) spatial sum
__device__ float g_Kch[CC*CC*25];       // K_change [c][a][x*5+y]
__device__ float g_W2[CC*CC*25];        // conv2 weights [o][i][t]

// ---------------- packed f32x2 helpers ----------------
__device__ __forceinline__ ull pack2(float x, float y) {
    ull r; asm("mov.b64 %0, {%1,%2};" : "=l"(r) : "f"(x), "f"(y)); return r;
}
__device__ __forceinline__ void ffma2(ull& d, ull a, ull b) {
    asm("fma.rn.f32x2 %0, %1, %2, %3;" : "=l"(d) : "l"(a), "l"(b), "l"(d));
}
__device__ __forceinline__ float2 unpk(ull v) {
    float2 r; asm("mov.b64 {%0,%1}, %2;" : "=f"(r.x), "=f"(r.y) : "l"(v)); return r;
}

// symm_pad(.,2) index map on a 56 axis
__device__ __forceinline__ int m56(int h) {
    return h < 2 ? 3 - h : (h >= 54 ? 107 - h : h);
}
// pad_activations row/col map on the 60 axis
__device__ __forceinline__ int m60(int r) {
    return r < 4 ? 5 - r : (r < 56 ? r - 2 : 109 - r);
}

// ---------------- kernel 1: Ab + per-channel sums (+ zero g_Kch) -----------
__global__ void __launch_bounds__(224) k_prep(const float* __restrict__ A,
                                              const float* __restrict__ noise) {
    int bid = blockIdx.x;              // b*128 + c
    int tid = threadIdx.x;
    {
        int z0 = bid*200;
        if (tid < 200) g_Kch[z0 + tid] = 0.f;
    }
    int b = bid >> 7, c = bid & 127;
    int f = c & 31;
    const float* Ap = A + (size_t)(b*FM + f)*HW;
    const float* Np = noise + (size_t)bid*HW;
    float* Op = g_Ab + (size_t)bid*HW;

    int h0 = tid / 56, w0 = tid - (tid/56)*56;
    int mw = m56(w0);
    float sum = 0.f;
    #pragma unroll
    for (int j = 0; j < 14; j++) {
        int h = h0 + j*4;
        int idx = h*56 + w0;
        float v = fmaxf(Ap[m56(h)*56 + mw] + ETA*Np[idx], 0.f);
        Op[idx] = v;
        sum += v;
    }
    __shared__ float red[7];
    #pragma unroll
    for (int o = 16; o; o >>= 1) sum += __shfl_xor_sync(~0u, sum, o);
    if ((tid & 31) == 0) red[tid >> 5] = sum;
    __syncthreads();
    if (tid < 32) {
        float s2 = (tid < 7) ? red[tid] : 0.f;
        #pragma unroll
        for (int o = 4; o; o >>= 1) s2 += __shfl_xor_sync(0xffu, s2, o);
        if (tid == 0) g_s[bid] = s2;
    }
}

// ---------------- K_change (R8 version, best known) ------------------------
// grid (b=16, cwt=2, at=4) = 128 blocks; 256 threads:
// warp = 2 winners x 16 a-pairs; block = 16 winners x 32 channels
#define CHS 34
#define SAB_FLOATS (6*60*CHS)            // 12240
#define SAM_ULL (2*16*56)
#define SMEM_KCH (SAB_FLOATS*4 + SAM_ULL*8)   // 63296 B

__global__ void __launch_bounds__(256) k_kch() {
    int b = blockIdx.x, cwt = blockIdx.y, at = blockIdx.z;
    int tid = threadIdx.x;
    int lane = tid & 31, wid = tid >> 5;
    int al = lane & 15;
    int cl = wid*2 + (lane >> 4);
    int a0 = at*32;

    extern __shared__ char smraw[];
    float* sAb  = (float*)smraw;                      // [6][60][34]
    ull*   sAm2 = (ull*)(smraw + SAB_FLOATS*4);       // [2][16][56]
    __shared__ int sC[16];

    if (tid < 16) {
        int f = cwt*16 + tid;
        float best = g_s[b*CC + f]; int wr = 0;
        #pragma unroll
        for (int r = 1; r < 4; r++) {
            float v = g_s[b*CC + r*FM + f];
            if (v > best) { best = v; wr = r; }
        }
        sC[tid] = wr*FM + f;
    }
    for (int i = tid; i < SAB_FLOATS; i += 256) sAb[i] = 0.f;
    __syncthreads();

    const float* AbB = g_Ab + (size_t)b*CC*HW;

    for (int r = 0; r < 3; r++)
        for (int idx = tid; idx < 32*56; idx += 256) {
            int ch = idx / 56, col = idx - ch*56;
            sAb[(r*60 + col + 2)*CHS + ch] = AbB[(size_t)(a0+ch)*HW + r*56 + col];
        }
    for (int idx = tid; idx < 16*56; idx += 256) {
        int cj = idx / 56, col = idx - cj*56;
        float v = AbB[(size_t)sC[cj]*HW + col];
        sAm2[cj*56 + col] = pack2(v, v);
    }
    int myc = sC[cl];
    __syncthreads();

    ull acc[5][5];
    #pragma unroll
    for (int x = 0; x < 5; x++)
        #pragma unroll
        for (int y = 0; y < 5; y++) acc[x][y] = 0ull;

    for (int h = 0; h < 56; h++) {
        float pf[7];
        int prow = h + 3;
        bool pv = prow < 56;
        #pragma unroll
        for (int j = 0; j < 7; j++) {
            int idx = tid + j*256;
            int ch = idx / 56, col = idx - ch*56;
            pf[j] = pv ? AbB[(size_t)(a0+ch)*HW + prow*56 + col] : 0.f;
        }
        float pa[4];
        int arow = h + 1;
        #pragma unroll
        for (int j = 0; j < 4; j++) {
            int idx = tid + j*256;
            pa[j] = 0.f;
            if (arow < 56 && idx < 16*56) {
                int cj = idx / 56, co = idx - cj*56;
                pa[j] = AbB[(size_t)sC[cj]*HW + arow*56 + co];
            }
        }

        const char* rxp[5];
        #pragma unroll
        for (int x = 0; x < 5; x++) {
            int slot = (h + 8 - x) % 6;
            rxp[x] = (const char*)(sAb + slot*60*CHS + 2*al);
        }
        const ull* am = sAm2 + (size_t)(h & 1)*16*56 + cl*56;

        ull rg[5][5];
        #pragma unroll
        for (int x = 0; x < 5; x++)
            #pragma unroll
            for (int j = 0; j < 5; j++)
                rg[x][j] = *(const ull*)(rxp[x] + j*(CHS*4));

        #pragma unroll 1
        for (int wb = 0; wb < 55; wb += 5) {
            #pragma unroll
            for (int k = 0; k < 5; k++) {
                ull a = am[wb + k];
                #pragma unroll
                for (int x = 0; x < 5; x++) {
                    #pragma unroll
                    for (int y = 0; y < 5; y++)
                        ffma2(acc[x][y], a, rg[x][(k + 4 - y) % 5]);
                    rg[x][k] = *(const ull*)(rxp[x] + (wb + k + 5)*(CHS*4));
                }
            }
        }
        {
            ull a = am[55];
            #pragma unroll
            for (int x = 0; x < 5; x++)
                #pragma unroll
                for (int y = 0; y < 5; y++)
                    ffma2(acc[x][y], a, rg[x][(4 - y) % 5]);
        }

        {
            int slot = (h + 3) % 6;
            #pragma unroll
            for (int j = 0; j < 7; j++) {
                int idx = tid + j*256;
                int ch = idx / 56, col = idx - ch*56;
                sAb[(slot*60 + col + 2)*CHS + ch] = pf[j];
            }
            if (arow < 56) {
                ull* dst = sAm2 + (size_t)(arow & 1)*16*56;
                #pragma unroll
                for (int j = 0; j < 4; j++) {
                    int idx = tid + j*256;
                    if (idx < 16*56) {
                        int cj = idx / 56, co = idx - cj*56;
                        dst[cj*56 + co] = pack2(pa[j], pa[j]);
                    }
                }
            }
        }
        __syncthreads();
    }

    float* dst = g_Kch + ((size_t)myc*CC + (a0 + 2*al))*25;
    #pragma unroll
    for (int x = 0; x < 5; x++)
        #pragma unroll
        for (int y = 0; y < 5; y++) {
            float2 v = unpk(acc[x][y]);
            atomicAdd(&dst[x*5 + y],      v.x * (1.f/2048.f));
            atomicAdd(&dst[25 + x*5 + y], v.y * (1.f/2048.f));
        }
}

// ---------------- W2 = minmax(0.9*K1 + 0.1*minmax(K_change)) ---------------
__global__ void k_w2(const float* __restrict__ K) {
    int g = blockIdx.x*blockDim.x + threadIdx.x;
    if (g >= CC*CC) return;
    int o = g >> 7, i = g & 127;
    const float* kch = g_Kch + ((size_t)i*CC + o)*25;
    float v[25];
    float mn = 1e30f, mx = -1e30f;
    #pragma unroll
    for (int t = 0; t < 25; t++) { v[t] = kch[t]; mn = fminf(mn, v[t]); mx = fmaxf(mx, v[t]); }
    float inv = 1.f / (mx - mn + EPSF);
    const float* kk = K + ((size_t)o*CC + i)*25;   // K1[i][o] = K[o][i]
    float mn2 = 1e30f, mx2 = -1e30f;
    #pragma unroll
    for (int t = 0; t < 25; t++) {
        v[t] = (1.f - ALPHA_)*kk[t] + ALPHA_*((v[t] - mn)*inv);
        mn2 = fminf(mn2, v[t]); mx2 = fmaxf(mx2, v[t]);
    }
    float inv2 = 1.f / (mx2 - mn2 + EPSF);
    float* w = g_W2 + (size_t)g*25;
    #pragma unroll
    for (int t = 0; t < 25; t++) w[t] = (v[t] - mn2)*inv2;
}

// ---------------- k_out v2: q-paired FFMA2, packed v, no reduction --------
// grid (b=16, pc=7) = 112 blocks; 512 threads = 8 rows x 2 warps.
// thread = 2 f (pair fp) x 14 q (group qg); all 32 i serial in-thread.
#define SIN_F (12*32*64)               // 24576 floats
#define SWF   (32*801)                 // 25632 floats
#define SMEM_OUT ((SIN_F + SWF)*4)     // 200832 B

__global__ void __launch_bounds__(512) k_out(float* __restrict__ out) {
    int b = blockIdx.x, pc = blockIdx.y;   // pc 0..6
    int p0 = pc * 8;
    int tid = threadIdx.x;
    int w = tid >> 5, lane = tid & 31;
    int pl = w >> 1;                   // local row 0..7
    int half = w & 1;
    int fp = lane >> 1;                // f-pair 0..15
    int qg = half*2 + (lane & 1);      // 0..3
    int q0 = qg * 14;

    extern __shared__ float sf[];
    float* sIn = sf;                   // [12][32][64] plain floats
    float* sW  = sf + SIN_F;           // [32][801]
    __shared__ int sFm[32];
    if (tid < 32) {
        float best = g_s[b*CC + tid]; int wr = 0;
        #pragma unroll
        for (int r = 1; r < 4; r++) {
            float v = g_s[b*CC + r*FM + tid];
            if (v > best) { best = v; wr = r; }
        }
        sFm[tid] = wr*FM + tid;
    }
    __syncthreads();

    // weights (scalar): sW[f][i*25+t]
    for (int idx = tid; idx < 32*800; idx += 512) {
        int f = idx / 800, r = idx - f*800;
        int i = r / 25, t = r - i*25;
        sW[f*801 + r] = g_W2[((size_t)sFm[f]*CC + sFm[i])*25 + t];
    }
    const float* AbB = g_Ab + (size_t)b*CC*HW;
    // all 12 padded rows for this chunk
    for (int idx = tid; idx < 12*32*60; idx += 512) {
        int r = idx / 1920, rem = idx - r*1920;
        int i = rem / 60, col = rem - i*60;
        int sr = m60(p0 + r);
        sIn[(r*32 + i)*64 + col] = AbB[(size_t)sFm[i]*HW + sr*56 + m60(col)];
    }
    __syncthreads();

    ull acc[2][7];
    #pragma unroll
    for (int ff = 0; ff < 2; ff++)
        #pragma unroll
        for (int j = 0; j < 7; j++) acc[ff][j] = 0ull;

    int f0 = 2*fp;
    const float* wb0 = sW + f0*801;
    const float* wb1 = wb0 + 801;

    #pragma unroll 1
    for (int i = 0; i < 32; i++) {
        #pragma unroll
        for (int u = 0; u < 5; u++) {
            const float* vr = sIn + ((pl + u)*32 + i)*64 + q0;
            // 9 aligned pairs (packed v) + 8 odd pairs via MOV
            ull ve[9];
            #pragma unroll
            for (int k = 0; k < 9; k++) ve[k] = *(const ull*)(vr + 2*k);
            ull vp[17];
            #pragma unroll
            for (int k = 0; k < 9; k++) vp[2*k] = ve[k];
            #pragma unroll
            for (int k = 0; k < 8; k++) {
                float2 a = unpk(ve[k]);
                float2 c = unpk(ve[k+1]);
                vp[2*k+1] = pack2(a.y, c.x);
            }
            // duplicated weights from scalar loads
            const float* wr0 = wb0 + i*25 + u*5;
            const float* wr1 = wb1 + i*25 + u*5;
            ull wd[2][5];
            #pragma unroll
            for (int y = 0; y < 5; y++) {
                float a = wr0[y]; wd[0][y] = pack2(a, a);
                float c = wr1[y]; wd[1][y] = pack2(c, c);
            }
            #pragma unroll
            for (int ff = 0; ff < 2; ff++)
                #pragma unroll
                for (int y = 0; y < 5; y++) {
                    ull wv = wd[ff][y];
                    #pragma unroll
                    for (int j = 0; j < 7; j++)
                        ffma2(acc[ff][j], vp[2*j + y], wv);
                }
        }
    }

    // epilogue: gather + scaled add, vectorized stores
    int p = p0 + pl;
    #pragma unroll
    for (int ff = 0; ff < 2; ff++) {
        int f = f0 + ff;
        const float2* ar = (const float2*)(AbB + (size_t)sFm[f]*HW + p*56 + q0);
        float2* orow = (float2*)(out + ((size_t)(b*FM + f)*56 + p)*56 + q0);
        #pragma unroll
        for (int j = 0; j < 7; j++) {
            float2 v = unpk(acc[ff][j]);
            float2 a = ar[j];
            float2 o;
            o.x = a.x + THETA_ * (v.x * (1.f/32.f));
            o.y = a.y + THETA_ * (v.y * (1.f/32.f));
            orow[j] = o;
        }
    }
}

// ---------------- launch ----------------
extern "C" void kernel_launch(void* const* d_in, const int* in_sizes, int n_in,
                              void* d_out, int out_size) {
    const float* A     = (const float*)d_in[0];
    const float* K     = (const float*)d_in[1];
    const float* noise = (const float*)d_in[2];
    float* out = (float*)d_out;

    k_prep<<<BB*CC, 224>>>(A, noise);

    cudaFuncSetAttribute(k_kch, cudaFuncAttributeMaxDynamicSharedMemorySize, SMEM_KCH);
    k_kch<<<dim3(BB, 2, 4), 256, SMEM_KCH>>>();

    k_w2<<<128, 128>>>(K);

    cudaFuncSetAttribute(k_out, cudaFuncAttributeMaxDynamicSharedMemorySize, SMEM_OUT);
    k_out<<<dim3(BB, 7), 512, SMEM_OUT>>>(out);
}

// round 11
// speedup vs baseline: 1.2439x; 1.0012x over previous
#include <cuda_runtime.h>
#include <cstdint>

#define BB 16
#define FM 32
#define CC 128
#define HW 3136
#define ETA 0.1f
#define ALPHA_ 0.1f
#define THETA_ 0.1f
#define EPSF 1e-10f

typedef unsigned long long ull;

// ------------- scratch (static device globals; no allocation) -------------
__device__ float g_Ab[BB*CC*HW];        // clip(tile(symm_pad(A,2)) + eta*noise, 0)
__device__ float g_s[BB*CC];            // per-(b,c) spatial sum
__device__ float g_Kch[CC*CC*25];       // K_change [c][a][x*5+y]
__device__ float g_W2[CC*CC*25];        // conv2 weights [o][i][t]

// ---------------- packed f32x2 helpers ----------------
__device__ __forceinline__ ull pack2(float x, float y) {
    ull r; asm("mov.b64 %0, {%1,%2};" : "=l"(r) : "f"(x), "f"(y)); return r;
}
__device__ __forceinline__ void ffma2(ull& d, ull a, ull b) {
    asm("fma.rn.f32x2 %0, %1, %2, %3;" : "=l"(d) : "l"(a), "l"(b), "l"(d));
}
__device__ __forceinline__ float2 unpk(ull v) {
    float2 r; asm("mov.b64 {%0,%1}, %2;" : "=f"(r.x), "=f"(r.y) : "l"(v)); return r;
}

// symm_pad(.,2) index map on a 56 axis
__device__ __forceinline__ int m56(int h) {
    return h < 2 ? 3 - h : (h >= 54 ? 107 - h : h);
}
// pad_activations row/col map on the 60 axis
__device__ __forceinline__ int m60(int r) {
    return r < 4 ? 5 - r : (r < 56 ? r - 2 : 109 - r);
}

// ---------------- kernel 1: Ab + per-channel sums (+ zero g_Kch) -----------
__global__ void __launch_bounds__(224) k_prep(const float* __restrict__ A,
                                              const float* __restrict__ noise) {
    int bid = blockIdx.x;              // b*128 + c
    int tid = threadIdx.x;
    {
        int z0 = bid*200;
        if (tid < 200) g_Kch[z0 + tid] = 0.f;
    }
    int b = bid >> 7, c = bid & 127;
    int f = c & 31;
    const float* Ap = A + (size_t)(b*FM + f)*HW;
    const float* Np = noise + (size_t)bid*HW;
    float* Op = g_Ab + (size_t)bid*HW;

    int h0 = tid / 56, w0 = tid - (tid/56)*56;
    int mw = m56(w0);
    float sum = 0.f;
    #pragma unroll
    for (int j = 0; j < 14; j++) {
        int h = h0 + j*4;
        int idx = h*56 + w0;
        float v = fmaxf(Ap[m56(h)*56 + mw] + ETA*Np[idx], 0.f);
        Op[idx] = v;
        sum += v;
    }
    __shared__ float red[7];
    #pragma unroll
    for (int o = 16; o; o >>= 1) sum += __shfl_xor_sync(~0u, sum, o);
    if ((tid & 31) == 0) red[tid >> 5] = sum;
    __syncthreads();
    if (tid < 32) {
        float s2 = (tid < 7) ? red[tid] : 0.f;
        #pragma unroll
        for (int o = 4; o; o >>= 1) s2 += __shfl_xor_sync(0xffu, s2, o);
        if (tid == 0) g_s[bid] = s2;
    }
}

// ---------------- K_change (R8 version, best known) ------------------------
#define CHS 34
#define SAB_FLOATS (6*60*CHS)            // 12240
#define SAM_ULL (2*16*56)
#define SMEM_KCH (SAB_FLOATS*4 + SAM_ULL*8)   // 63296 B

__global__ void __launch_bounds__(256) k_kch() {
    int b = blockIdx.x, cwt = blockIdx.y, at = blockIdx.z;
    int tid = threadIdx.x;
    int lane = tid & 31, wid = tid >> 5;
    int al = lane & 15;
    int cl = wid*2 + (lane >> 4);
    int a0 = at*32;

    extern __shared__ char smraw[];
    float* sAb  = (float*)smraw;                      // [6][60][34]
    ull*   sAm2 = (ull*)(smraw + SAB_FLOATS*4);       // [2][16][56]
    __shared__ int sC[16];

    if (tid < 16) {
        int f = cwt*16 + tid;
        float best = g_s[b*CC + f]; int wr = 0;
        #pragma unroll
        for (int r = 1; r < 4; r++) {
            float v = g_s[b*CC + r*FM + f];
            if (v > best) { best = v; wr = r; }
        }
        sC[tid] = wr*FM + f;
    }
    for (int i = tid; i < SAB_FLOATS; i += 256) sAb[i] = 0.f;
    __syncthreads();

    const float* AbB = g_Ab + (size_t)b*CC*HW;

    for (int r = 0; r < 3; r++)
        for (int idx = tid; idx < 32*56; idx += 256) {
            int ch = idx / 56, col = idx - ch*56;
            sAb[(r*60 + col + 2)*CHS + ch] = AbB[(size_t)(a0+ch)*HW + r*56 + col];
        }
    for (int idx = tid; idx < 16*56; idx += 256) {
        int cj = idx / 56, col = idx - cj*56;
        float v = AbB[(size_t)sC[cj]*HW + col];
        sAm2[cj*56 + col] = pack2(v, v);
    }
    int myc = sC[cl];
    __syncthreads();

    ull acc[5][5];
    #pragma unroll
    for (int x = 0; x < 5; x++)
        #pragma unroll
        for (int y = 0; y < 5; y++) acc[x][y] = 0ull;

    for (int h = 0; h < 56; h++) {
        float pf[7];
        int prow = h + 3;
        bool pv = prow < 56;
        #pragma unroll
        for (int j = 0; j < 7; j++) {
            int idx = tid + j*256;
            int ch = idx / 56, col = idx - ch*56;
            pf[j] = pv ? AbB[(size_t)(a0+ch)*HW + prow*56 + col] : 0.f;
        }
        float pa[4];
        int arow = h + 1;
        #pragma unroll
        for (int j = 0; j < 4; j++) {
            int idx = tid + j*256;
            pa[j] = 0.f;
            if (arow < 56 && idx < 16*56) {
                int cj = idx / 56, co = idx - cj*56;
                pa[j] = AbB[(size_t)sC[cj]*HW + arow*56 + co];
            }
        }

        const char* rxp[5];
        #pragma unroll
        for (int x = 0; x < 5; x++) {
            int slot = (h + 8 - x) % 6;
            rxp[x] = (const char*)(sAb + slot*60*CHS + 2*al);
        }
        const ull* am = sAm2 + (size_t)(h & 1)*16*56 + cl*56;

        ull rg[5][5];
        #pragma unroll
        for (int x = 0; x < 5; x++)
            #pragma unroll
            for (int j = 0; j < 5; j++)
                rg[x][j] = *(const ull*)(rxp[x] + j*(CHS*4));

        #pragma unroll 1
        for (int wb = 0; wb < 55; wb += 5) {
            #pragma unroll
            for (int k = 0; k < 5; k++) {
                ull a = am[wb + k];
                #pragma unroll
                for (int x = 0; x < 5; x++) {
                    #pragma unroll
                    for (int y = 0; y < 5; y++)
                        ffma2(acc[x][y], a, rg[x][(k + 4 - y) % 5]);
                    rg[x][k] = *(const ull*)(rxp[x] + (wb + k + 5)*(CHS*4));
                }
            }
        }
        {
            ull a = am[55];
            #pragma unroll
            for (int x = 0; x < 5; x++)
                #pragma unroll
                for (int y = 0; y < 5; y++)
                    ffma2(acc[x][y], a, rg[x][(4 - y) % 5]);
        }

        {
            int slot = (h + 3) % 6;
            #pragma unroll
            for (int j = 0; j < 7; j++) {
                int idx = tid + j*256;
                int ch = idx / 56, col = idx - ch*56;
                sAb[(slot*60 + col + 2)*CHS + ch] = pf[j];
            }
            if (arow < 56) {
                ull* dst = sAm2 + (size_t)(arow & 1)*16*56;
                #pragma unroll
                for (int j = 0; j < 4; j++) {
                    int idx = tid + j*256;
                    if (idx < 16*56) {
                        int cj = idx / 56, co = idx - cj*56;
                        dst[cj*56 + co] = pack2(pa[j], pa[j]);
                    }
                }
            }
        }
        __syncthreads();
    }

    float* dst = g_Kch + ((size_t)myc*CC + (a0 + 2*al))*25;
    #pragma unroll
    for (int x = 0; x < 5; x++)
        #pragma unroll
        for (int y = 0; y < 5; y++) {
            float2 v = unpk(acc[x][y]);
            atomicAdd(&dst[x*5 + y],      v.x * (1.f/2048.f));
            atomicAdd(&dst[25 + x*5 + y], v.y * (1.f/2048.f));
        }
}

// ---------------- W2 = minmax(0.9*K1 + 0.1*minmax(K_change)) ---------------
__global__ void k_w2(const float* __restrict__ K) {
    int g = blockIdx.x*blockDim.x + threadIdx.x;
    if (g >= CC*CC) return;
    int o = g >> 7, i = g & 127;
    const float* kch = g_Kch + ((size_t)i*CC + o)*25;
    float v[25];
    float mn = 1e30f, mx = -1e30f;
    #pragma unroll
    for (int t = 0; t < 25; t++) { v[t] = kch[t]; mn = fminf(mn, v[t]); mx = fmaxf(mx, v[t]); }
    float inv = 1.f / (mx - mn + EPSF);
    const float* kk = K + ((size_t)o*CC + i)*25;   // K1[i][o] = K[o][i]
    float mn2 = 1e30f, mx2 = -1e30f;
    #pragma unroll
    for (int t = 0; t < 25; t++) {
        v[t] = (1.f - ALPHA_)*kk[t] + ALPHA_*((v[t] - mn)*inv);
        mn2 = fminf(mn2, v[t]); mx2 = fmaxf(mx2, v[t]);
    }
    float inv2 = 1.f / (mx2 - mn2 + EPSF);
    float* w = g_W2 + (size_t)g*25;
    #pragma unroll
    for (int t = 0; t < 25; t++) w[t] = (v[t] - mn2)*inv2;
}

// ---------------- k_out v3: stride-28 q-pairing, zero repack MOVs ----------
// grid (b=16, pc=7) = 112 blocks; 256 threads = 8 rows x 1 warp.
// lane = 16 f-pairs x 2 q-groups; acc[j] = {out[q0+j], out[q0+28+j]}.
// sP[r][i][c] = {v60[c], v60[c+28]} -> every tap read is one aligned LDS.
#define SP_ULL (12*32*32)              // 12288
#define SWF3   (32*801)                // 25632 floats
#define SMEM_OUT (SP_ULL*8 + SWF3*4)   // 98304 + 102528 = 200832 B

__global__ void __launch_bounds__(256) k_out(float* __restrict__ out) {
    int b = blockIdx.x, pc = blockIdx.y;   // pc 0..6
    int p0 = pc * 8;
    int tid = threadIdx.x;
    int pl = tid >> 5;                 // local output row 0..7
    int lane = tid & 31;
    int fp = lane & 15;                // f-pair -> f = 2fp, 2fp+1
    int qg = lane >> 4;                // 0,1
    int q0 = qg * 14;

    extern __shared__ ull sh[];
    ull*   sP = sh;                    // [12][32][32] {v[c], v[c+28]}
    float* sW = (float*)(sh + SP_ULL); // [32][801] scalar weights
    __shared__ int sFm[32];
    if (tid < 32) {
        float best = g_s[b*CC + tid]; int wr = 0;
        #pragma unroll
        for (int r = 1; r < 4; r++) {
            float v = g_s[b*CC + r*FM + tid];
            if (v > best) { best = v; wr = r; }
        }
        sFm[tid] = wr*FM + tid;
    }
    __syncthreads();

    // weights: sW[f][i*25+t]
    for (int idx = tid; idx < 32*800; idx += 256) {
        int f = idx / 800, r = idx - f*800;
        int i = r / 25, t = r - i*25;
        sW[f*801 + r] = g_W2[((size_t)sFm[f]*CC + sFm[i])*25 + t];
    }

    const float* AbB = g_Ab + (size_t)b*CC*HW;
    // sP fill: 12 padded rows, strided pairs
    for (int idx = tid; idx < 12*32*32; idx += 256) {
        int r = idx >> 10;             // /1024
        int rem = idx & 1023;
        int i = rem >> 5, c = rem & 31;
        int sr = m60(p0 + r);
        const float* src = AbB + (size_t)sFm[i]*HW + sr*56;
        sP[idx] = pack2(src[m60(c)], src[m60(c + 28)]);
    }
    __syncthreads();

    ull acc[2][14];
    #pragma unroll
    for (int ff = 0; ff < 2; ff++)
        #pragma unroll
        for (int j = 0; j < 14; j++) acc[ff][j] = 0ull;

    const float* wb0 = sW + (2*fp)*801;
    const float* wb1 = wb0 + 801;

    #pragma unroll 1
    for (int i = 0; i < 32; i++) {
        #pragma unroll
        for (int u = 0; u < 5; u++) {
            const ull* vp = sP + (size_t)((pl + u)*32 + i)*32 + q0;
            ull v[18];
            #pragma unroll
            for (int k = 0; k < 9; k++) {
                ulonglong2 t2 = *(const ulonglong2*)(vp + 2*k);
                v[2*k] = t2.x; v[2*k+1] = t2.y;
            }
            const float* wr0 = wb0 + i*25 + u*5;
            const float* wr1 = wb1 + i*25 + u*5;
            #pragma unroll
            for (int y = 0; y < 5; y++) {
                float a0 = wr0[y], a1 = wr1[y];
                ull w0 = pack2(a0, a0), w1 = pack2(a1, a1);
                #pragma unroll
                for (int j = 0; j < 14; j++) {
                    ffma2(acc[0][j], v[j + y], w0);
                    ffma2(acc[1][j], v[j + y], w1);
                }
            }
        }
    }

    // epilogue: gather + scaled add
    int p = p0 + pl;
    #pragma unroll
    for (int ff = 0; ff < 2; ff++) {
        int f = 2*fp + ff;
        const float* ar = AbB + (size_t)sFm[f]*HW + p*56;
        float* orow = out + ((size_t)(b*FM + f)*56 + p)*56;
        #pragma unroll
        for (int j = 0; j < 14; j++) {
            float2 vv = unpk(acc[ff][j]);
            orow[q0 + j]      = ar[q0 + j]      + THETA_ * (vv.x * (1.f/32.f));
            orow[q0 + 28 + j] = ar[q0 + 28 + j] + THETA_ * (vv.y * (1.f/32.f));
        }
    }
}

// ---------------- launch ----------------
extern "C" void kernel_launch(void* const* d_in, const int* in_sizes, int n_in,
                              void* d_out, int out_size) {
    const float* A     = (const float*)d_in[0];
    const float* K     = (const float*)d_in[1];
    const float* noise = (const float*)d_in[2];
    float* out = (float*)d_out;

    k_prep<<<BB*CC, 224>>>(A, noise);

    cudaFuncSetAttribute(k_kch, cudaFuncAttributeMaxDynamicSharedMemorySize, SMEM_KCH);
    k_kch<<<dim3(BB, 2, 4), 256, SMEM_KCH>>>();

    k_w2<<<128, 128>>>(K);

    cudaFuncSetAttribute(k_out, cudaFuncAttributeMaxDynamicSharedMemorySize, SMEM_OUT);
    k_out<<<dim3(BB, 7), 256, SMEM_OUT>>>(out);
}